// round 16
// baseline (speedup 1.0000x reference)
#include <cuda_runtime.h>
#include <cuda_bf16.h>
#include <math.h>
#include <stdint.h>

#define HW      131072      // 256*512
#define W_IMG   512
#define H_IMG   256
#define NC      256
#define NB      2
#define NOUT    16          // 13 pos + 1 reg + 2 off

typedef unsigned long long ull;

// Scratch for evident = relu(pos conv): [2,13,H,W]
__device__ float g_ev[NB * 13 * HW];

// ---------------- compile-time Hough region geometry ----------------
__host__ __device__ constexpr int region_of(int ys, int xs) {
    int r2 = ys * ys + xs * xs;
    if (r2 <= 4) return 0;
    int ring = (r2 <= 64) ? 0 : (r2 <= 256) ? 1 : 2;
    int bin = 0;
    if (ys > 0)      bin = (xs > 0) ? 0 : 1;
    else if (ys < 0) bin = (xs < 0) ? 2 : 3;
    else             bin = (xs > 0) ? 0 : 2;   // ys==0 row (origin is r2<=4)
    return 1 + ring * 4 + bin;
}

struct SegTab {
    short iy[512];
    short a[512];
    short b[512];
    int   start[14];
    float w[13];
};

__host__ __device__ constexpr SegTab make_segs() {
    SegTab t{};
    int cnt[13] = {};
    for (int iy = 0; iy < 33; iy++)
        for (int ix = 0; ix < 33; ix++)
            cnt[region_of(16 - iy, 16 - ix)]++;
    int pos = 0;
    for (int r = 0; r < 13; r++) {
        t.start[r] = pos;
        t.w[r] = 1.0f / (float)cnt[r];
        for (int iy = 0; iy < 33; iy++) {
            int ix = 0;
            while (ix < 33) {
                if (region_of(16 - iy, 16 - ix) == r) {
                    int a0 = ix;
                    while (ix < 33 && region_of(16 - iy, 16 - ix) == r) ix++;
                    t.iy[pos] = (short)iy;
                    t.a[pos]  = (short)a0;
                    t.b[pos]  = (short)(ix - 1);
                    pos++;
                } else ix++;
            }
        }
    }
    t.start[13] = pos;
    return t;
}

// ================= small PTX helpers (all sm_80-baseline) =================
__device__ __forceinline__ uint32_t smem_u32(const void* p) {
    uint32_t a;
    asm("{ .reg .u64 t; cvta.to.shared.u64 t, %1; cvt.u32.u64 %0, t; }"
        : "=r"(a) : "l"(p));
    return a;
}
// pack {lo=bf16(f0), hi=bf16(f1)}  (PTX: cvt d, a, b -> d.hi=cvt(a), d.lo=cvt(b))
#define PACK_BF16X2(res, f0, f1) \
    asm("cvt.rn.bf16x2.f32 %0, %1, %2;" : "=r"(res) : "f"(f1), "f"(f0))
#define STS128(r0, r1, r2, r3, sm_addr) \
    asm volatile("st.shared.v4.b32 [%0], {%1, %2, %3, %4};" \
        :: "r"(sm_addr), "r"(r0), "r"(r1), "r"(r2), "r"(r3) : "memory")
#define LDMATRIX_X4(a0, a1, a2, a3, addr) \
    asm volatile("ldmatrix.sync.aligned.m8n8.x4.shared.b16 {%0,%1,%2,%3}, [%4];" \
        : "=r"(a0), "=r"(a1), "=r"(a2), "=r"(a3) : "r"(addr))
#define MMA_BF16(d, a, b0v, b1v) \
    asm volatile("mma.sync.aligned.m16n8k16.row.col.f32.bf16.bf16.f32 " \
        "{%0,%1,%2,%3}, {%4,%5,%6,%7}, {%8,%9}, {%0,%1,%2,%3};" \
        : "+f"((d)[0]), "+f"((d)[1]), "+f"((d)[2]), "+f"((d)[3]) \
        : "r"((a)[0]), "r"((a)[1]), "r"((a)[2]), "r"((a)[3]), \
          "r"(b0v), "r"(b1v))

// ---------------- Kernel A: mma.sync bf16 split-precision 1x1 convs -------
// D[128px, 16out] per tile. A = x (bf16 hi/lo) staged in SMEM, row stride
// 528B (33 quads -> STS.128 staging and ldmatrix both bank-conflict-free).
// B = weights as prepacked u32 fragment tables. 3 split passes in f32 accum.
// 148 blocks x 512 thr, contiguous tile ranges (TLB-safe, ~80 pages/block).
#define ASTRIDE   528                     // bytes per A row (264 bf16)
#define OFF_ALO   67584                   // 128*528
#define OFF_WFH   135168
#define OFF_WFL   143360
#define DSM_BYTES 151552
#define NTILES    2048                    // NB*HW/128

__global__ void __launch_bounds__(512, 1) k_head_mma(
    const float* __restrict__ x,
    const float* __restrict__ pos_w, const float* __restrict__ pos_b,
    const float* __restrict__ reg_w, const float* __restrict__ reg_b,
    const float* __restrict__ off_w, const float* __restrict__ off_b,
    float* __restrict__ out)
{
    extern __shared__ __align__(16) char dsm[];
    __shared__ float s_bias[16];

    const int tid  = threadIdx.x;
    const int wid  = tid >> 5;
    const int lane = tid & 31;
    const int bk   = blockIdx.x;

    const uint32_t sbA  = smem_u32(dsm);           // A_hi base
    uint32_t* wfh = reinterpret_cast<uint32_t*>(dsm + OFF_WFH);
    uint32_t* wfl = reinterpret_cast<uint32_t*>(dsm + OFF_WFL);

    // ---- build B fragment tables (once) ----
    // entry i: nt=i>>10, kc=(i>>6)&15, sl=i&63 (half=sl>>5, l5=sl&31,
    // tq=l5&3, g=l5>>2). ch = kc*16 + 2tq + 8*half, o = nt*8+g.
    for (int i = tid; i < 2048; i += 512) {
        int nt = i >> 10, kc = (i >> 6) & 15, sl = i & 63;
        int half = sl >> 5, l5 = sl & 31;
        int tq = l5 & 3, g = l5 >> 2;
        int ch = kc * 16 + 2 * tq + 8 * half;
        int o  = nt * 8 + g;
        float w0 = (o < 13) ? pos_w[o * NC + ch]
                 : (o == 13) ? reg_w[ch] : off_w[(o - 14) * NC + ch];
        float w1 = (o < 13) ? pos_w[o * NC + ch + 1]
                 : (o == 13) ? reg_w[ch + 1] : off_w[(o - 14) * NC + ch + 1];
        uint32_t hp; PACK_BF16X2(hp, w0, w1);
        float g0 = __uint_as_float(hp << 16);
        float g1 = __uint_as_float(hp & 0xFFFF0000u);
        uint32_t lp; PACK_BF16X2(lp, w0 - g0, w1 - g1);
        wfh[i] = hp;
        wfl[i] = lp;
    }
    if (tid < 16)
        s_bias[tid] = (tid < 13) ? pos_b[tid] : (tid == 13) ? reg_b[0] : off_b[tid - 14];
    __syncthreads();

    // ---- tile loop: contiguous range per block ----
    const int t0 = (bk * 512) / 37;          // bk*NTILES/148
    const int t1 = ((bk + 1) * 512) / 37;

    // mma sub-tile assignment: 8 m-tiles x 2 n-tiles
    const int mi = wid & 7, nt = wid >> 3;
    const int g  = lane >> 2, tq = lane & 3;
    // ldmatrix source row/col for this lane
    const int lm_row = 16 * mi + (lane & 7) + ((lane >> 3) & 1) * 8;
    const int lm_col = (lane >> 4) * 16;     // byte offset for k+8 half

    for (int t = t0; t < t1; ++t) {
        const int bimg = t >> 10;
        const int px0  = (t & 1023) * 128;
        const float* xb = x + (size_t)bimg * NC * HW + px0;

        // ---- stage A: 128px x 256ch -> bf16 hi/lo ----
        // warp wid covers ch-groups {wid, wid+16} (8 ch each), 4 px-quads.
        #pragma unroll
        for (int cg2 = 0; cg2 < 2; cg2++) {
            const int ch0 = (wid + 16 * cg2) * 8;
            #pragma unroll
            for (int q = 0; q < 4; q++) {
                const int px = 32 * q + lane;
                float f[8];
                #pragma unroll
                for (int j = 0; j < 8; j++)
                    f[j] = xb[(size_t)(ch0 + j) * HW + px];
                uint32_t hp[4], lp[4];
                #pragma unroll
                for (int p = 0; p < 4; p++) {
                    PACK_BF16X2(hp[p], f[2 * p], f[2 * p + 1]);
                    float g0 = __uint_as_float(hp[p] << 16);
                    float g1 = __uint_as_float(hp[p] & 0xFFFF0000u);
                    PACK_BF16X2(lp[p], f[2 * p] - g0, f[2 * p + 1] - g1);
                }
                const uint32_t so = (uint32_t)px * ASTRIDE + (uint32_t)ch0 * 2;
                STS128(hp[0], hp[1], hp[2], hp[3], sbA + so);
                STS128(lp[0], lp[1], lp[2], lp[3], sbA + OFF_ALO + so);
            }
        }
        __syncthreads();

        // ---- mma: 16 k-chunks x 3 split passes ----
        float d[4] = {0.f, 0.f, 0.f, 0.f};
        const uint32_t arow = sbA + (uint32_t)lm_row * ASTRIDE + lm_col;
        const int wbase = (nt * 16) * 64 + lane;
        #pragma unroll
        for (int kc = 0; kc < 16; kc++) {
            uint32_t ah[4], al[4];
            LDMATRIX_X4(ah[0], ah[1], ah[2], ah[3], arow + kc * 32);
            LDMATRIX_X4(al[0], al[1], al[2], al[3], arow + OFF_ALO + kc * 32);
            uint32_t bh0 = wfh[wbase + kc * 64];
            uint32_t bh1 = wfh[wbase + kc * 64 + 32];
            uint32_t bl0 = wfl[wbase + kc * 64];
            uint32_t bl1 = wfl[wbase + kc * 64 + 32];
            MMA_BF16(d, ah, bh0, bh1);
            MMA_BF16(d, ah, bl0, bl1);
            MMA_BF16(d, al, bh0, bh1);
        }

        // ---- epilogue: route D to ev / out ----
        {
            const int r0 = px0 + 16 * mi + g;
            const int o0 = nt * 8 + 2 * tq;
            #pragma unroll
            for (int h = 0; h < 4; h++) {
                const int o  = o0 + (h & 1);
                const int px = r0 + (h >> 1) * 8;
                float v = d[h] + s_bias[o];
                if (o < 13) {
                    g_ev[(size_t)(bimg * 13 + o) * HW + px] = fmaxf(v, 0.f);
                } else if (o == 13) {
                    out[2 * HW + (size_t)bimg * HW + px] = v;
                } else {
                    out[4 * HW + (size_t)(bimg * 2 + (o - 14)) * HW + px] = v;
                }
            }
        }
        __syncthreads();   // protect A rewrite next iteration
    }
}

// ---------------- Kernel B: Hough vote conv + sigmoid (R14, 23.6us) -------
#define PSTR 68

template<int R>
__device__ __forceinline__ void scan_store(
    int b, int y0, int x0, int lane, int wrp, float* __restrict__ buf)
{
    const float* ev = g_ev + (size_t)(b * 13 + R) * HW;
    const int seg = lane >> 4;
    const int sl  = lane & 15;
    const int row = 2 * wrp + seg;
    const int gy  = y0 + row - 16;
    const int gx  = x0 + sl * 4 - 16;

    float4 v = make_float4(0.f, 0.f, 0.f, 0.f);
    if ((unsigned)gy < (unsigned)H_IMG && (unsigned)gx <= (unsigned)(W_IMG - 4))
        v = *reinterpret_cast<const float4*>(ev + gy * W_IMG + gx);

    float s  = ((v.x + v.y) + (v.z + v.w));
    float inc = s;
    #pragma unroll
    for (int d = 1; d < 16; d <<= 1) {
        float n = __shfl_up_sync(0xffffffffu, inc, d, 16);
        if (sl >= d) inc += n;
    }
    float excl = inc - s;

    float* rowp = buf + row * PSTR;
    float4 pq;
    pq.x = excl;
    pq.y = excl + v.x;
    pq.z = pq.y + v.y;
    pq.w = pq.z + v.z;
    *reinterpret_cast<float4*>(rowp + 4 * sl) = pq;
    if (sl == 15) rowp[64] = inc;
}

template<int R>
__device__ __forceinline__ float gather_region(const float* __restrict__ buf, int pbase) {
    constexpr SegTab t = make_segs();
    constexpr int j0 = t.start[R];
    constexpr int j1 = t.start[R + 1];
    float s0 = 0.f, s1 = 0.f, s2 = 0.f, s3 = 0.f;
    #pragma unroll
    for (int j = j0; j < j1; j++) {
        int ro = t.iy[j] * PSTR;
        float d = buf[pbase + ro + t.b[j] + 1] - buf[pbase + ro + t.a[j]];
        int lane4 = j & 3;
        if      (lane4 == 0) s0 += d;
        else if (lane4 == 1) s1 += d;
        else if (lane4 == 2) s2 += d;
        else                 s3 += d;
    }
    return ((s0 + s1) + (s2 + s3)) * t.w[R];
}

template<int R> struct ChanLoop {
    static __device__ __forceinline__ float run(
        int b, int y0, int x0, int lane, int wrp, int pbase,
        float* __restrict__ sP0, float* __restrict__ sP1)
    {
        float* buf = (R & 1) ? sP1 : sP0;
        scan_store<R>(b, y0, x0, lane, wrp, buf);
        __syncthreads();
        float part = gather_region<R>(buf, pbase);
        return part + ChanLoop<R + 1>::run(b, y0, x0, lane, wrp, pbase, sP0, sP1);
    }
};

template<> struct ChanLoop<13> {
    static __device__ __forceinline__ float run(int, int, int, int, int, int, float*, float*) {
        return 0.f;
    }
};

__global__ void __launch_bounds__(1024) k_hough(float* __restrict__ out)
{
    __shared__ __align__(16) float sP[2][64 * PSTR];

    const int tid  = threadIdx.x;
    const int lane = tid & 31;
    const int wrp  = tid >> 5;
    const int b  = blockIdx.z;
    const int y0 = blockIdx.y * 32;
    const int x0 = blockIdx.x * 32;
    const int pbase = wrp * PSTR + lane;

    float score = ChanLoop<0>::run(b, y0, x0, lane, wrp, pbase, sP[0], sP[1]);

    out[(size_t)b * HW + (y0 + wrp) * W_IMG + (x0 + lane)] =
        1.f / (1.f + __expf(-score));
}

// ---------------- launch ----------------
extern "C" void kernel_launch(void* const* d_in, const int* in_sizes, int n_in,
                              void* d_out, int out_size)
{
    const float* x     = (const float*)d_in[0];
    const float* pos_w = (const float*)d_in[1];
    const float* pos_b = (const float*)d_in[2];
    const float* reg_w = (const float*)d_in[3];
    const float* reg_b = (const float*)d_in[4];
    const float* off_w = (const float*)d_in[5];
    const float* off_b = (const float*)d_in[6];
    float* out = (float*)d_out;

    cudaFuncSetAttribute(k_head_mma, cudaFuncAttributeMaxDynamicSharedMemorySize,
                         DSM_BYTES);

    k_head_mma<<<148, 512, DSM_BYTES>>>(x, pos_w, pos_b, reg_w, reg_b,
                                        off_w, off_b, out);

    dim3 gB(W_IMG / 32, H_IMG / 32, NB);
    k_hough<<<gB, 1024>>>(out);
}

// round 17
// speedup vs baseline: 1.1081x; 1.1081x over previous
#include <cuda_runtime.h>
#include <cuda_bf16.h>
#include <math.h>
#include <stdint.h>

#define HW      131072      // 256*512
#define W_IMG   512
#define H_IMG   256
#define NC      256
#define NB      2
#define NOUT    16          // 13 pos + 1 reg + 2 off

typedef unsigned long long ull;

// Scratch for evident = relu(pos conv): [2,13,H,W]
__device__ float g_ev[NB * 13 * HW];

// ---------------- compile-time Hough region geometry ----------------
__host__ __device__ constexpr int region_of(int ys, int xs) {
    int r2 = ys * ys + xs * xs;
    if (r2 <= 4) return 0;
    int ring = (r2 <= 64) ? 0 : (r2 <= 256) ? 1 : 2;
    int bin = 0;
    if (ys > 0)      bin = (xs > 0) ? 0 : 1;
    else if (ys < 0) bin = (xs < 0) ? 2 : 3;
    else             bin = (xs > 0) ? 0 : 2;   // ys==0 row (origin is r2<=4)
    return 1 + ring * 4 + bin;
}

struct SegTab {
    short iy[512];
    short a[512];
    short b[512];
    int   start[14];
    float w[13];
};

__host__ __device__ constexpr SegTab make_segs() {
    SegTab t{};
    int cnt[13] = {};
    for (int iy = 0; iy < 33; iy++)
        for (int ix = 0; ix < 33; ix++)
            cnt[region_of(16 - iy, 16 - ix)]++;
    int pos = 0;
    for (int r = 0; r < 13; r++) {
        t.start[r] = pos;
        t.w[r] = 1.0f / (float)cnt[r];
        for (int iy = 0; iy < 33; iy++) {
            int ix = 0;
            while (ix < 33) {
                if (region_of(16 - iy, 16 - ix) == r) {
                    int a0 = ix;
                    while (ix < 33 && region_of(16 - iy, 16 - ix) == r) ix++;
                    t.iy[pos] = (short)iy;
                    t.a[pos]  = (short)a0;
                    t.b[pos]  = (short)(ix - 1);
                    pos++;
                } else ix++;
            }
        }
    }
    t.start[13] = pos;
    return t;
}

// ================= small PTX helpers (all sm_80-baseline) =================
__device__ __forceinline__ uint32_t smem_u32(const void* p) {
    uint32_t a;
    asm("{ .reg .u64 t; cvta.to.shared.u64 t, %1; cvt.u32.u64 %0, t; }"
        : "=r"(a) : "l"(p));
    return a;
}
#define PACK_BF16X2(res, f0, f1) \
    asm("cvt.rn.bf16x2.f32 %0, %1, %2;" : "=r"(res) : "f"(f1), "f"(f0))
#define STS128(r0, r1, r2, r3, sm_addr) \
    asm volatile("st.shared.v4.b32 [%0], {%1, %2, %3, %4};" \
        :: "r"(sm_addr), "r"(r0), "r"(r1), "r"(r2), "r"(r3) : "memory")
#define LDMATRIX_X4(a0, a1, a2, a3, addr) \
    asm volatile("ldmatrix.sync.aligned.m8n8.x4.shared.b16 {%0,%1,%2,%3}, [%4];" \
        : "=r"(a0), "=r"(a1), "=r"(a2), "=r"(a3) : "r"(addr))
#define MMA_BF16(d, a, b0v, b1v) \
    asm volatile("mma.sync.aligned.m16n8k16.row.col.f32.bf16.bf16.f32 " \
        "{%0,%1,%2,%3}, {%4,%5,%6,%7}, {%8,%9}, {%0,%1,%2,%3};" \
        : "+f"((d)[0]), "+f"((d)[1]), "+f"((d)[2]), "+f"((d)[3]) \
        : "r"((a)[0]), "r"((a)[1]), "r"((a)[2]), "r"((a)[3]), \
          "r"(b0v), "r"(b1v))
#define BARSYNC(id, cnt) \
    asm volatile("bar.sync %0, %1;" :: "r"(id), "r"(cnt) : "memory")

// ---------------- Kernel A: mma.sync bf16 split, two-team overlap ---------
// Two independent 8-warp teams per block, each on its own 64-px tiles with
// team-local named barriers -> one team's staging LDGs overlap the other
// team's mma. Per team: 4 m-tiles x 2 n-tiles; A (bf16 hi/lo) row stride
// 528B (conflict-free STS.128 + ldmatrix); B as prepacked fragment tables.
#define ASTRIDE   528                     // bytes per A row (264 bf16)
#define TEAMHALF  33792                   // 64 rows * 528
#define TEAMBUF   67584                   // hi + lo
#define OFF_WFH   135168
#define OFF_WFL   143360
#define DSM_BYTES 151552
#define NTILES    4096                    // NB*HW/64

__global__ void __launch_bounds__(512, 1) k_head_mma(
    const float* __restrict__ x,
    const float* __restrict__ pos_w, const float* __restrict__ pos_b,
    const float* __restrict__ reg_w, const float* __restrict__ reg_b,
    const float* __restrict__ off_w, const float* __restrict__ off_b,
    float* __restrict__ out)
{
    extern __shared__ __align__(16) char dsm[];
    __shared__ float s_bias[16];

    const int tid  = threadIdx.x;
    const int wid  = tid >> 5;
    const int lane = tid & 31;
    const int bk   = blockIdx.x;

    uint32_t* wfh = reinterpret_cast<uint32_t*>(dsm + OFF_WFH);
    uint32_t* wfl = reinterpret_cast<uint32_t*>(dsm + OFF_WFL);

    // ---- build B fragment tables (once; validated in R16) ----
    for (int i = tid; i < 2048; i += 512) {
        int nt = i >> 10, kc = (i >> 6) & 15, sl = i & 63;
        int half = sl >> 5, l5 = sl & 31;
        int tq = l5 & 3, g = l5 >> 2;
        int ch = kc * 16 + 2 * tq + 8 * half;
        int o  = nt * 8 + g;
        float w0 = (o < 13) ? pos_w[o * NC + ch]
                 : (o == 13) ? reg_w[ch] : off_w[(o - 14) * NC + ch];
        float w1 = (o < 13) ? pos_w[o * NC + ch + 1]
                 : (o == 13) ? reg_w[ch + 1] : off_w[(o - 14) * NC + ch + 1];
        uint32_t hp; PACK_BF16X2(hp, w0, w1);
        float g0 = __uint_as_float(hp << 16);
        float g1 = __uint_as_float(hp & 0xFFFF0000u);
        uint32_t lp; PACK_BF16X2(lp, w0 - g0, w1 - g1);
        wfh[i] = hp;
        wfl[i] = lp;
    }
    if (tid < 16)
        s_bias[tid] = (tid < 13) ? pos_b[tid] : (tid == 13) ? reg_b[0] : off_b[tid - 14];
    __syncthreads();

    // ---- team decomposition ----
    const int team  = wid >> 3;            // 0 or 1
    const int tw    = wid & 7;             // warp within team
    const int barid = 1 + team;
    const uint32_t teamA = smem_u32(dsm) + (uint32_t)team * TEAMBUF;

    // mma sub-tile: 4 m-tiles x 2 n-tiles per team
    const int mi = tw & 3, nt = tw >> 2;
    const int g  = lane >> 2, tq = lane & 3;
    const int lm_row = 16 * mi + (lane & 7) + ((lane >> 3) & 1) * 8;
    const int lm_col = (lane >> 4) * 16;
    const uint32_t arow = teamA + (uint32_t)lm_row * ASTRIDE + lm_col;
    const int wbase = (nt * 16) * 64 + lane;

    // contiguous tile range per block; teams alternate tiles within it
    const int t0 = (bk * 1024) / 37;       // bk*NTILES/148
    const int t1 = ((bk + 1) * 1024) / 37;

    for (int t = t0 + team; t < t1; t += 2) {
        const int bimg = t >> 11;                     // 2048 tiles per batch
        const int px0  = (t & 2047) << 6;             // 64 px per tile
        const float* xb = x + (size_t)bimg * NC * HW + px0;

        // ---- stage A: 64px x 256ch -> bf16 hi/lo (team-local buffer) ----
        #pragma unroll
        for (int cg = 0; cg < 4; cg++) {
            const int ch0 = tw * 8 + cg * 64;
            #pragma unroll
            for (int q = 0; q < 2; q++) {
                const int px = 32 * q + lane;
                float f[8];
                #pragma unroll
                for (int j = 0; j < 8; j++)
                    f[j] = xb[(size_t)(ch0 + j) * HW + px];
                uint32_t hp[4], lp[4];
                #pragma unroll
                for (int p = 0; p < 4; p++) {
                    PACK_BF16X2(hp[p], f[2 * p], f[2 * p + 1]);
                    float g0 = __uint_as_float(hp[p] << 16);
                    float g1 = __uint_as_float(hp[p] & 0xFFFF0000u);
                    PACK_BF16X2(lp[p], f[2 * p] - g0, f[2 * p + 1] - g1);
                }
                const uint32_t so = (uint32_t)px * ASTRIDE + (uint32_t)ch0 * 2;
                STS128(hp[0], hp[1], hp[2], hp[3], teamA + so);
                STS128(lp[0], lp[1], lp[2], lp[3], teamA + TEAMHALF + so);
            }
        }
        BARSYNC(barid, 256);

        // ---- mma: 16 k-chunks x 3 split passes ----
        float d[4] = {0.f, 0.f, 0.f, 0.f};
        #pragma unroll
        for (int kc = 0; kc < 16; kc++) {
            uint32_t ah[4], al[4];
            LDMATRIX_X4(ah[0], ah[1], ah[2], ah[3], arow + kc * 32);
            LDMATRIX_X4(al[0], al[1], al[2], al[3], arow + TEAMHALF + kc * 32);
            uint32_t bh0 = wfh[wbase + kc * 64];
            uint32_t bh1 = wfh[wbase + kc * 64 + 32];
            uint32_t bl0 = wfl[wbase + kc * 64];
            uint32_t bl1 = wfl[wbase + kc * 64 + 32];
            MMA_BF16(d, ah, bh0, bh1);
            MMA_BF16(d, ah, bl0, bl1);
            MMA_BF16(d, al, bh0, bh1);
        }

        // ---- epilogue ----
        {
            const int r0 = px0 + 16 * mi + g;
            const int o0 = nt * 8 + 2 * tq;
            #pragma unroll
            for (int h = 0; h < 4; h++) {
                const int o  = o0 + (h & 1);
                const int px = r0 + (h >> 1) * 8;
                float v = d[h] + s_bias[o];
                if (o < 13) {
                    g_ev[(size_t)(bimg * 13 + o) * HW + px] = fmaxf(v, 0.f);
                } else if (o == 13) {
                    out[2 * HW + (size_t)bimg * HW + px] = v;
                } else {
                    out[4 * HW + (size_t)(bimg * 2 + (o - 14)) * HW + px] = v;
                }
            }
        }
        BARSYNC(barid, 256);   // protect team buffer rewrite next iteration
    }
}

// ---------------- Kernel B: Hough vote conv + sigmoid (R14, 23.6us) -------
#define PSTR 68

template<int R>
__device__ __forceinline__ void scan_store(
    int b, int y0, int x0, int lane, int wrp, float* __restrict__ buf)
{
    const float* ev = g_ev + (size_t)(b * 13 + R) * HW;
    const int seg = lane >> 4;
    const int sl  = lane & 15;
    const int row = 2 * wrp + seg;
    const int gy  = y0 + row - 16;
    const int gx  = x0 + sl * 4 - 16;

    float4 v = make_float4(0.f, 0.f, 0.f, 0.f);
    if ((unsigned)gy < (unsigned)H_IMG && (unsigned)gx <= (unsigned)(W_IMG - 4))
        v = *reinterpret_cast<const float4*>(ev + gy * W_IMG + gx);

    float s  = ((v.x + v.y) + (v.z + v.w));
    float inc = s;
    #pragma unroll
    for (int d = 1; d < 16; d <<= 1) {
        float n = __shfl_up_sync(0xffffffffu, inc, d, 16);
        if (sl >= d) inc += n;
    }
    float excl = inc - s;

    float* rowp = buf + row * PSTR;
    float4 pq;
    pq.x = excl;
    pq.y = excl + v.x;
    pq.z = pq.y + v.y;
    pq.w = pq.z + v.z;
    *reinterpret_cast<float4*>(rowp + 4 * sl) = pq;
    if (sl == 15) rowp[64] = inc;
}

template<int R>
__device__ __forceinline__ float gather_region(const float* __restrict__ buf, int pbase) {
    constexpr SegTab t = make_segs();
    constexpr int j0 = t.start[R];
    constexpr int j1 = t.start[R + 1];
    float s0 = 0.f, s1 = 0.f, s2 = 0.f, s3 = 0.f;
    #pragma unroll
    for (int j = j0; j < j1; j++) {
        int ro = t.iy[j] * PSTR;
        float d = buf[pbase + ro + t.b[j] + 1] - buf[pbase + ro + t.a[j]];
        int lane4 = j & 3;
        if      (lane4 == 0) s0 += d;
        else if (lane4 == 1) s1 += d;
        else if (lane4 == 2) s2 += d;
        else                 s3 += d;
    }
    return ((s0 + s1) + (s2 + s3)) * t.w[R];
}

template<int R> struct ChanLoop {
    static __device__ __forceinline__ float run(
        int b, int y0, int x0, int lane, int wrp, int pbase,
        float* __restrict__ sP0, float* __restrict__ sP1)
    {
        float* buf = (R & 1) ? sP1 : sP0;
        scan_store<R>(b, y0, x0, lane, wrp, buf);
        __syncthreads();
        float part = gather_region<R>(buf, pbase);
        return part + ChanLoop<R + 1>::run(b, y0, x0, lane, wrp, pbase, sP0, sP1);
    }
};

template<> struct ChanLoop<13> {
    static __device__ __forceinline__ float run(int, int, int, int, int, int, float*, float*) {
        return 0.f;
    }
};

__global__ void __launch_bounds__(1024) k_hough(float* __restrict__ out)
{
    __shared__ __align__(16) float sP[2][64 * PSTR];

    const int tid  = threadIdx.x;
    const int lane = tid & 31;
    const int wrp  = tid >> 5;
    const int b  = blockIdx.z;
    const int y0 = blockIdx.y * 32;
    const int x0 = blockIdx.x * 32;
    const int pbase = wrp * PSTR + lane;

    float score = ChanLoop<0>::run(b, y0, x0, lane, wrp, pbase, sP[0], sP[1]);

    out[(size_t)b * HW + (y0 + wrp) * W_IMG + (x0 + lane)] =
        1.f / (1.f + __expf(-score));
}

// ---------------- launch ----------------
extern "C" void kernel_launch(void* const* d_in, const int* in_sizes, int n_in,
                              void* d_out, int out_size)
{
    const float* x     = (const float*)d_in[0];
    const float* pos_w = (const float*)d_in[1];
    const float* pos_b = (const float*)d_in[2];
    const float* reg_w = (const float*)d_in[3];
    const float* reg_b = (const float*)d_in[4];
    const float* off_w = (const float*)d_in[5];
    const float* off_b = (const float*)d_in[6];
    float* out = (float*)d_out;

    cudaFuncSetAttribute(k_head_mma, cudaFuncAttributeMaxDynamicSharedMemorySize,
                         DSM_BYTES);

    k_head_mma<<<148, 512, DSM_BYTES>>>(x, pos_w, pos_b, reg_w, reg_b,
                                        off_w, off_b, out);

    dim3 gB(W_IMG / 32, H_IMG / 32, NB);
    k_hough<<<gB, 1024>>>(out);
}